// round 12
// baseline (speedup 1.0000x reference)
#include <cuda_runtime.h>
#include <cuda_bf16.h>
#include <cstddef>

#define COL    4096
#define TPB    128
#define WPB    (TPB/32)       // 4 warps per block, one row per warp
#define NCHUNK 16             // 16 chunks x 256 elements (1 KB per warp-chunk)
#define F4C    64             // float4 per chunk
#define SMEM_BYTES (WPB * COL * 4)   // 64 KB: one full row per warp

// Reciprocal table 1/(i+1), filled each launch (graph-capturable, no allocs).
__device__ float g_rinv[COL];

__global__ void rinv_init_kernel() {
    int i = blockIdx.x * blockDim.x + threadIdx.x;
    if (i < COL) g_rinv[i] = 1.0f / (float)(i + 1);
}

__device__ __forceinline__ void cp_async_16(unsigned dst_smem, const void* src) {
    asm volatile("cp.async.cg.shared.global [%0], [%1], 16;"
                 :: "r"(dst_smem), "l"(src));
}
__device__ __forceinline__ void stg_32(float4* p, float4 a, float4 b) {
    unsigned long long q0 = ((unsigned long long)__float_as_uint(a.y) << 32) | __float_as_uint(a.x);
    unsigned long long q1 = ((unsigned long long)__float_as_uint(a.w) << 32) | __float_as_uint(a.z);
    unsigned long long q2 = ((unsigned long long)__float_as_uint(b.y) << 32) | __float_as_uint(b.x);
    unsigned long long q3 = ((unsigned long long)__float_as_uint(b.w) << 32) | __float_as_uint(b.z);
    asm volatile("st.global.L2::evict_first.v4.b64 [%0], {%1,%2,%3,%4};"
                 :: "l"(p), "l"(q0), "l"(q1), "l"(q2), "l"(q3) : "memory");
}

extern __shared__ float4 sbuf[];   // [WPB][1024] float4, warp-private rows

__global__ __launch_bounds__(TPB) void layernorm_v2_kernel(
    const float* __restrict__ x,
    const float* __restrict__ alpha,
    const float* __restrict__ beta,
    float* __restrict__ out)
{
    const int lane = threadIdx.x & 31;
    const int wid  = threadIdx.x >> 5;
    const size_t row = (size_t)blockIdx.x * WPB + wid;

    const float4* xr  = (const float4*)(x + row * COL);
    const float4* rr  = (const float4*)g_rinv;
    float4*       orw = (float4*)(out + row * COL);
    float4*       sw  = sbuf + wid * (COL / 4);   // this warp's 16 KB region

    // ---- fire the ENTIRE row as cp.async: 16 groups, 2 x 16B per lane each ----
    // chunk c layout: slotA f4[c*64 + lane] (512B), slotB f4[c*64 + 32 + lane]
    #pragma unroll
    for (int c = 0; c < NCHUNK; ++c) {
        const float4* srcA = xr + c * F4C + 2 * lane;   // contiguous 32B per lane
        unsigned dstA = (unsigned)__cvta_generic_to_shared(sw + c * F4C + lane);
        unsigned dstB = (unsigned)__cvta_generic_to_shared(sw + c * F4C + 32 + lane);
        cp_async_16(dstA, srcA);
        cp_async_16(dstB, srcA + 1);
        asm volatile("cp.async.commit_group;");
    }

    float carry = 0.0f;   // row prefix entering current chunk
    float acc   = 0.0f;   // variance accumulator

    // ---- pass 1: consume in 4 phases of 4 chunks behind wait_group ----
    #pragma unroll
    for (int ph = 0; ph < 4; ++ph) {
        if      (ph == 0) asm volatile("cp.async.wait_group 12;");
        else if (ph == 1) asm volatile("cp.async.wait_group 8;");
        else if (ph == 2) asm volatile("cp.async.wait_group 4;");
        else              asm volatile("cp.async.wait_group 0;");

        #pragma unroll
        for (int j = 0; j < 4; ++j) {
            const int c = ph * 4 + j;
            const float4 c0 = sw[c * F4C + lane];        // lane's own copies
            const float4 c1 = sw[c * F4C + 32 + lane];
            const float4 r0 = rr[c * F4C + 2 * lane];    // L1-resident table
            const float4 r1 = rr[c * F4C + 2 * lane + 1];

            // local inclusive scan of the 8-chunk
            const float p0 = c0.x;
            const float p1 = p0 + c0.y;
            const float p2 = p1 + c0.z;
            const float p3 = p2 + c0.w;
            const float p4 = p3 + c1.x;
            const float p5 = p4 + c1.y;
            const float p6 = p5 + c1.z;
            const float p7 = p6 + c1.w;
            const float tot = p7;

            // warp scan of lane totals
            float v = tot;
            #pragma unroll
            for (int o = 1; o < 32; o <<= 1) {
                float t = __shfl_up_sync(0xffffffffu, v, o);
                if (lane >= o) v += t;
            }
            const float chunk_total = __shfl_sync(0xffffffffu, v, 31);
            const float excl = carry + (v - tot);

            float d0 = c0.x - (excl + p0) * r0.x;
            float d1 = c0.y - (excl + p1) * r0.y;
            float d2 = c0.z - (excl + p2) * r0.z;
            float d3 = c0.w - (excl + p3) * r0.w;
            float d4 = c1.x - (excl + p4) * r1.x;
            float d5 = c1.y - (excl + p5) * r1.y;
            float d6 = c1.z - (excl + p6) * r1.z;
            float d7 = c1.w - (excl + p7) * r1.w;
            acc += ((d0 * d0 + d1 * d1) + (d2 * d2 + d3 * d3))
                 + ((d4 * d4 + d5 * d5) + (d6 * d6 + d7 * d7));

            carry += chunk_total;
        }
    }

    // ---- warp-local stats (no barriers anywhere) ----
    #pragma unroll
    for (int o = 16; o > 0; o >>= 1) acc += __shfl_xor_sync(0xffffffffu, acc, o);

    const float var   = acc   * (1.0f / (float)(COL - 1));
    const float mean  = carry * (1.0f / (float)COL);
    const float scale = __ldg(alpha) * rsqrtf(var + 1e-5f);
    const float shift = __ldg(beta) - mean * scale;    // out = x*scale + shift

    // ---- pass 2: read row from smem, 32B coalesced streaming stores ----
    #pragma unroll 4
    for (int c = 0; c < NCHUNK; ++c) {
        float4 a = sw[c * F4C + lane];
        float4 b = sw[c * F4C + 32 + lane];
        float4 oa, ob;
        oa.x = a.x * scale + shift;
        oa.y = a.y * scale + shift;
        oa.z = a.z * scale + shift;
        oa.w = a.w * scale + shift;
        ob.x = b.x * scale + shift;
        ob.y = b.y * scale + shift;
        ob.z = b.z * scale + shift;
        ob.w = b.w * scale + shift;
        stg_32(orw + c * F4C + 2 * lane, oa, ob);
    }
}

extern "C" void kernel_launch(void* const* d_in, const int* in_sizes, int n_in,
                              void* d_out, int out_size)
{
    const float* x     = (const float*)d_in[0];
    const float* alpha = (const float*)d_in[1];
    const float* beta  = (const float*)d_in[2];
    float*       out   = (float*)d_out;

    const int rows = in_sizes[0] / COL;
    const int grid = rows / WPB;                 // 8192 blocks x 4 warp-rows

    static int smem_set = 0;
    if (!smem_set) {
        cudaFuncSetAttribute(layernorm_v2_kernel,
                             cudaFuncAttributeMaxDynamicSharedMemorySize,
                             SMEM_BYTES);
        smem_set = 1;
    }

    rinv_init_kernel<<<(COL + 255) / 256, 256>>>();
    layernorm_v2_kernel<<<grid, TPB, SMEM_BYTES>>>(x, alpha, beta, out);
}

// round 13
// speedup vs baseline: 1.4611x; 1.4611x over previous
#include <cuda_runtime.h>
#include <cuda_bf16.h>
#include <cstddef>

#define COL    4096
#define TPB    256
#define WPB    (TPB/32)     // 8 warps per block, one row per warp
#define NPAIR  8            // 8 pairs of 256-element chunks
#define F4C    64           // float4 per chunk

// Tables filled each launch (graph-capturable, no allocs).
__device__ float g_rinv[COL];          // 1/(i+1)
__device__ float g_csum[16 * 32];      // per (chunk, lane): sum r^2 over lane's 8

__global__ void table_init_kernel() {
    int i = blockIdx.x * blockDim.x + threadIdx.x;
    if (i < COL) g_rinv[i] = 1.0f / (float)(i + 1);
    if (i < 16 * 32) {
        int c = i >> 5, ln = i & 31;
        float s = 0.0f;
        #pragma unroll
        for (int j = 0; j < 8; ++j) {
            float r = 1.0f / (float)(c * 256 + ln * 8 + j + 1);
            s += r * r;
        }
        g_csum[i] = s;
    }
}

// ---- 32-byte L2-steered accesses (.v4.b64 required for evict hints) ----
__device__ __forceinline__ void ldg_el_32(const float4* p, float4& a, float4& b) {
    unsigned long long q0, q1, q2, q3;
    asm volatile("ld.global.nc.L2::evict_last.v4.b64 {%0,%1,%2,%3}, [%4];"
                 : "=l"(q0), "=l"(q1), "=l"(q2), "=l"(q3) : "l"(p));
    a.x = __uint_as_float((unsigned)q0); a.y = __uint_as_float((unsigned)(q0 >> 32));
    a.z = __uint_as_float((unsigned)q1); a.w = __uint_as_float((unsigned)(q1 >> 32));
    b.x = __uint_as_float((unsigned)q2); b.y = __uint_as_float((unsigned)(q2 >> 32));
    b.z = __uint_as_float((unsigned)q3); b.w = __uint_as_float((unsigned)(q3 >> 32));
}
__device__ __forceinline__ void ldg_ef_32(const float4* p, float4& a, float4& b) {
    unsigned long long q0, q1, q2, q3;
    asm volatile("ld.global.nc.L2::evict_first.v4.b64 {%0,%1,%2,%3}, [%4];"
                 : "=l"(q0), "=l"(q1), "=l"(q2), "=l"(q3) : "l"(p));
    a.x = __uint_as_float((unsigned)q0); a.y = __uint_as_float((unsigned)(q0 >> 32));
    a.z = __uint_as_float((unsigned)q1); a.w = __uint_as_float((unsigned)(q1 >> 32));
    b.x = __uint_as_float((unsigned)q2); b.y = __uint_as_float((unsigned)(q2 >> 32));
    b.z = __uint_as_float((unsigned)q3); b.w = __uint_as_float((unsigned)(q3 >> 32));
}
__device__ __forceinline__ void stg_ef_32(float4* p, float4 a, float4 b) {
    unsigned long long q0 = ((unsigned long long)__float_as_uint(a.y) << 32) | __float_as_uint(a.x);
    unsigned long long q1 = ((unsigned long long)__float_as_uint(a.w) << 32) | __float_as_uint(a.z);
    unsigned long long q2 = ((unsigned long long)__float_as_uint(b.y) << 32) | __float_as_uint(b.x);
    unsigned long long q3 = ((unsigned long long)__float_as_uint(b.w) << 32) | __float_as_uint(b.z);
    asm volatile("st.global.L2::evict_first.v4.b64 [%0], {%1,%2,%3,%4};"
                 :: "l"(p), "l"(q0), "l"(q1), "l"(q2), "l"(q3) : "memory");
}

// Local scan + A/B accumulation for one 8-element chunk slice.
__device__ __forceinline__ void chunk_local(const float4 d0, const float4 d1,
                                            const float4 r0, const float4 r1,
                                            float& A, float& B, float& tot)
{
    float p, q;
    p = d0.x;        q = d0.x - p * r0.x; A  = q * q; B  = q * r0.x;
    p += d0.y;       q = d0.y - p * r0.y; A += q * q; B += q * r0.y;
    p += d0.z;       q = d0.z - p * r0.z; A += q * q; B += q * r0.z;
    p += d0.w;       q = d0.w - p * r0.w; A += q * q; B += q * r0.w;
    p += d1.x;       q = d1.x - p * r1.x; A += q * q; B += q * r1.x;
    p += d1.y;       q = d1.y - p * r1.y; A += q * q; B += q * r1.y;
    p += d1.z;       q = d1.z - p * r1.z; A += q * q; B += q * r1.z;
    p += d1.w;       q = d1.w - p * r1.w; A += q * q; B += q * r1.w;
    tot = p;
}

__global__ __launch_bounds__(TPB) void layernorm_v2_kernel(
    const float* __restrict__ x,
    const float* __restrict__ alpha,
    const float* __restrict__ beta,
    float* __restrict__ out)
{
    const int lane = threadIdx.x & 31;
    const int wid  = threadIdx.x >> 5;
    const size_t row = (size_t)blockIdx.x * WPB + wid;

    const float4* xr  = (const float4*)(x + row * COL);
    const float4* rr  = (const float4*)g_rinv;
    float4*       orw = (float4*)(out + row * COL);

    const int l2 = lane * 2;   // lane's 32B pair within a chunk

    // ---- pass 1: chunk-PAIRS with ILP-2 scans, double-buffered loads ----
    float4 a0, a1, b0, b1;                       // current pair (chunks 2p, 2p+1)
    ldg_el_32(xr + l2,       a0, a1);
    ldg_el_32(xr + F4C + l2, b0, b1);
    float carry = 0.0f;
    float acc   = 0.0f;

    #pragma unroll 1
    for (int p = 0; p < NPAIR; ++p) {
        const int cA = 2 * p, cB = 2 * p + 1;

        // prefetch next pair (stays in flight across this pair's compute)
        float4 na0, na1, nb0, nb1;
        if (p + 1 < NPAIR) {
            ldg_el_32(xr + (cA + 2) * F4C + l2, na0, na1);
            ldg_el_32(xr + (cB + 2) * F4C + l2, nb0, nb1);
        }

        // reciprocal slices (L1-resident) + per-chunk C constants
        const float4 ra0 = rr[cA * F4C + l2];
        const float4 ra1 = rr[cA * F4C + l2 + 1];
        const float4 rb0 = rr[cB * F4C + l2];
        const float4 rb1 = rr[cB * F4C + l2 + 1];
        const float  Ca  = g_csum[cA * 32 + lane];
        const float  Cb  = g_csum[cB * 32 + lane];

        // two independent local scans + A/B
        float Aa, Ba, ta, Ab, Bb, tb;
        chunk_local(a0, a1, ra0, ra1, Aa, Ba, ta);
        chunk_local(b0, b1, rb0, rb1, Ab, Bb, tb);

        // two interleaved warp scans (independent shfl chains)
        float va = ta, vb = tb;
        #pragma unroll
        for (int o = 1; o < 32; o <<= 1) {
            float sa = __shfl_up_sync(0xffffffffu, va, o);
            float sb = __shfl_up_sync(0xffffffffu, vb, o);
            if (lane >= o) { va += sa; vb += sb; }
        }
        const float totA = __shfl_sync(0xffffffffu, va, 31);
        const float totB = __shfl_sync(0xffffffffu, vb, 31);
        const float la = va - ta;
        const float lb = vb - tb;

        // carry joins AFTER both scans (scalar adds, not on shfl path)
        const float ea = carry + la;
        const float eb = carry + totA + lb;
        acc += (Aa - 2.0f * ea * Ba + ea * ea * Ca)
             + (Ab - 2.0f * eb * Bb + eb * eb * Cb);
        carry += totA + totB;

        a0 = na0; a1 = na1; b0 = nb0; b1 = nb1;
    }

    // ---- warp-local stats (no barriers anywhere) ----
    #pragma unroll
    for (int o = 16; o > 0; o >>= 1) acc += __shfl_xor_sync(0xffffffffu, acc, o);

    const float var   = acc   * (1.0f / (float)(COL - 1));
    const float mean  = carry * (1.0f / (float)COL);
    const float scale = __ldg(alpha) * rsqrtf(var + 1e-5f);
    const float shift = __ldg(beta) - mean * scale;    // out = x*scale + shift

    // ---- pass 2: re-read row (L2-pinned), release lines, stream stores ----
    #pragma unroll 4
    for (int c = 0; c < 2 * NPAIR; ++c) {
        float4 u, v;
        ldg_ef_32(xr + c * F4C + l2, u, v);
        float4 ou, ov;
        ou.x = u.x * scale + shift;
        ou.y = u.y * scale + shift;
        ou.z = u.z * scale + shift;
        ou.w = u.w * scale + shift;
        ov.x = v.x * scale + shift;
        ov.y = v.y * scale + shift;
        ov.z = v.z * scale + shift;
        ov.w = v.w * scale + shift;
        stg_ef_32(orw + c * F4C + l2, ou, ov);
    }
}

extern "C" void kernel_launch(void* const* d_in, const int* in_sizes, int n_in,
                              void* d_out, int out_size)
{
    const float* x     = (const float*)d_in[0];
    const float* alpha = (const float*)d_in[1];
    const float* beta  = (const float*)d_in[2];
    float*       out   = (float*)d_out;

    const int rows = in_sizes[0] / COL;
    const int grid = rows / WPB;                 // 4096 blocks x 8 warp-rows

    table_init_kernel<<<(COL + 255) / 256, 256>>>();
    layernorm_v2_kernel<<<grid, TPB>>>(x, alpha, beta, out);
}